// round 14
// baseline (speedup 1.0000x reference)
#include <cuda_runtime.h>
#include <cuda.h>
#include <cuda_fp16.h>
#include <cstdint>

#define T_LEN 128

// ---------------- scratch layout (floats) ----------------
#define OFF_PRE   0                                   // [32][1024] f32
#define OFF_EXP   (OFF_PRE  + 32*1024)                // [32][1024] f32
#define OFF_A0IN  (OFF_EXP  + 32*1024)                // [160][1024] f32
#define OFF_C0    (OFF_A0IN + 160*1024)               // [160][2048] f32
#define OFF_HB    (OFF_C0   + 160*2048)               // half: 2 sets x [2 d][2 pl][32][1024]
#define OFF_X1H   (OFF_HB   + 2*2*32*1024)            // half[4096][2048]
#define OFF_G1    (OFF_X1H  + 4096*1024)              // f32 [4096][2048]
#define OFF_OUT2H (OFF_G1   + 4096*2048)              // half[4096][2048]
#define OFF_PROJ  (OFF_OUT2H + 4096*1024)             // f32 [4096][512]
#define OFF_HEH   (OFF_PROJ + 4096*512)               // half[4096][512]
#define OFF_WIH1H (OFF_HEH  + 4096*256)               // half[2048][2048]
#define OFF_WP1H  (OFF_WIH1H + 2048*1024)             // half[512][2048]
#define OFF_WP2H  (OFF_WP1H  + 512*1024)              // half[32000][512]
#define SCRATCH_TOTAL (OFF_WP2H + 32000*256)

__device__ __align__(1024) float g_scratch[SCRATCH_TOTAL];
// tree barrier state: per-direction 8 leaf counters (128B apart), root, sense
__device__ unsigned g_leaf[2 * 8 * 32];
__device__ unsigned g_root[2 * 32];
__device__ unsigned g_sense[2 * 32];

// ---------------- helpers ----------------
__device__ __forceinline__ unsigned f2tf32(float f) {
    unsigned u;
    asm("cvt.rna.tf32.f32 %0, %1;" : "=r"(u) : "f"(f));
    return u;
}

__device__ __forceinline__ void mma_tf32(float c[4], const unsigned a[4], const unsigned b[2]) {
    asm volatile(
        "mma.sync.aligned.m16n8k8.row.col.f32.tf32.tf32.f32 "
        "{%0,%1,%2,%3}, {%4,%5,%6,%7}, {%8,%9}, {%0,%1,%2,%3};"
        : "+f"(c[0]), "+f"(c[1]), "+f"(c[2]), "+f"(c[3])
        : "r"(a[0]), "r"(a[1]), "r"(a[2]), "r"(a[3]), "r"(b[0]), "r"(b[1]));
}

__device__ __forceinline__ void mma_f16(float c[4], const unsigned a[4], const unsigned b[2]) {
    asm volatile(
        "mma.sync.aligned.m16n8k16.row.col.f32.f16.f16.f32 "
        "{%0,%1,%2,%3}, {%4,%5,%6,%7}, {%8,%9}, {%0,%1,%2,%3};"
        : "+f"(c[0]), "+f"(c[1]), "+f"(c[2]), "+f"(c[3])
        : "r"(a[0]), "r"(a[1]), "r"(a[2]), "r"(a[3]), "r"(b[0]), "r"(b[1]));
}

// ---------------- fp32 -> fp16 convert ----------------
__global__ __launch_bounds__(256) void tohalf_kernel(
    const float* __restrict__ in, __half2* __restrict__ out, int n4)
{
    for (int i = blockIdx.x * 256 + threadIdx.x; i < n4; i += gridDim.x * 256) {
        float4 v = ((const float4*)in)[i];
        out[2 * i]     = __floats2half2_rn(v.x, v.y);
        out[2 * i + 1] = __floats2half2_rn(v.z, v.w);
    }
}

// =================== TMA-fed fp16 GEMM (mma.sync f16, f32 accum) ===================
#define TG_STAGES 4
#define TG_STAGE_BYTES 49152                   // A 128*128B + B 256*128B
#define TG_SMEM_BYTES  (1024 + TG_STAGES * TG_STAGE_BYTES)

__device__ __forceinline__ uint32_t smem_u32(const void* p) {
    return (uint32_t)__cvta_generic_to_shared((void*)p);
}
__device__ __forceinline__ void tma2d(uint32_t sdst, const CUtensorMap* tm,
                                      int x, int y, uint32_t bar) {
    asm volatile(
        "cp.async.bulk.tensor.2d.shared::cta.global.tile.mbarrier::complete_tx::bytes "
        "[%0], [%1, {%2, %3}], [%4];"
        :: "r"(sdst), "l"(tm), "r"(x), "r"(y), "r"(bar) : "memory");
}
#define MBAR_INIT(a, c) \
    asm volatile("mbarrier.init.shared.b64 [%0], %1;" :: "r"(a), "r"(c) : "memory")
#define MBAR_EXPECT_TX(a, b) \
    asm volatile("mbarrier.arrive.expect_tx.shared.b64 _, [%0], %1;" :: "r"(a), "r"(b) : "memory")
#define MBAR_ARRIVE(a) \
    asm volatile("mbarrier.arrive.shared.b64 _, [%0];" :: "r"(a) : "memory")
#define MBAR_WAIT(a, ph) do { \
    uint32_t _d_; \
    asm volatile("{\n\t.reg .pred p;\n\tmbarrier.try_wait.parity.acquire.cta.shared::cta.b64 p, [%1], %2;\n\tselp.b32 %0, 1, 0, p;\n\t}" \
        : "=r"(_d_) : "r"(a), "r"(ph) : "memory"); \
    while (!_d_) { \
        asm volatile("{\n\t.reg .pred p;\n\tmbarrier.try_wait.parity.acquire.cta.shared::cta.b64 p, [%1], %2, 0x989680;\n\tselp.b32 %0, 1, 0, p;\n\t}" \
            : "=r"(_d_) : "r"(a), "r"(ph) : "memory"); \
    } \
} while (0)

__global__ __launch_bounds__(512, 1) void gemm_tma_f16_kernel(
    const __grid_constant__ CUtensorMap tmA,
    const __grid_constant__ CUtensorMap tmB,
    const float* __restrict__ bias, float* __restrict__ C,
    int N, int K)
{
    extern __shared__ char dsm[];
    __shared__ __align__(8) unsigned long long bars[8];  // full[4], empty[4]

    const int tid  = threadIdx.x;
    const int warp = tid >> 5;
    const int lane = tid & 31;
    const int wm   = warp & 3;
    const int wn   = warp >> 2;
    const int gid  = lane >> 2;
    const int tig  = lane & 3;
    const int mblk = blockIdx.y * 128;
    const int nblk = blockIdx.x * 256;
    const int KT   = K / 64;

    const uint32_t raw   = smem_u32(dsm);
    const uint32_t sbase = (raw + 1023) & ~1023u;
    char* tile0 = dsm + (sbase - raw);
    const uint32_t barb = smem_u32(bars);

    if (tid == 0) {
        for (int i = 0; i < 4; i++) MBAR_INIT(barb + i * 8, 1);
        for (int i = 4; i < 8; i++) MBAR_INIT(barb + i * 8, 16);
    }
    __syncthreads();

    if (tid == 0) {
        const int pre = KT < TG_STAGES ? KT : TG_STAGES;
        for (int st = 0; st < pre; st++) {
            const uint32_t full = barb + st * 8;
            MBAR_EXPECT_TX(full, TG_STAGE_BYTES);
            const uint32_t sa = sbase + st * TG_STAGE_BYTES;
            tma2d(sa,         &tmA, st * 64, mblk, full);
            tma2d(sa + 16384, &tmB, st * 64, nblk, full);
        }
    }

    float acc[2][8][4];
#pragma unroll
    for (int i = 0; i < 2; i++)
#pragma unroll
        for (int j = 0; j < 8; j++)
#pragma unroll
            for (int r = 0; r < 4; r++) acc[i][j][r] = 0.f;

    const uint32_t xorv = (uint32_t)gid << 4;

    for (int kt = 0; kt < KT; kt++) {
        const int st = kt & 3;
        const uint32_t ph = (kt >> 2) & 1;
        MBAR_WAIT(barb + st * 8, ph);

        const char* As = tile0 + st * TG_STAGE_BYTES;
        const char* Bs = As + 16384;

#pragma unroll
        for (int ks = 0; ks < 4; ks++) {
            const uint32_t c4a = (uint32_t)(ks * 32 + tig * 4) ^ xorv;
            const uint32_t c4b = (uint32_t)(ks * 32 + tig * 4 + 16) ^ xorv;
            unsigned afr[2][4], bfr[8][2];
#pragma unroll
            for (int mf = 0; mf < 2; mf++) {
                const int r0 = wm * 32 + mf * 16 + gid;
                afr[mf][0] = *(const unsigned*)(As + r0 * 128 + c4a);
                afr[mf][1] = *(const unsigned*)(As + (r0 + 8) * 128 + c4a);
                afr[mf][2] = *(const unsigned*)(As + r0 * 128 + c4b);
                afr[mf][3] = *(const unsigned*)(As + (r0 + 8) * 128 + c4b);
            }
#pragma unroll
            for (int nf = 0; nf < 8; nf++) {
                const int nc = wn * 64 + nf * 8 + gid;
                bfr[nf][0] = *(const unsigned*)(Bs + nc * 128 + c4a);
                bfr[nf][1] = *(const unsigned*)(Bs + nc * 128 + c4b);
            }
#pragma unroll
            for (int mf = 0; mf < 2; mf++)
#pragma unroll
                for (int nf = 0; nf < 8; nf++)
                    mma_f16(acc[mf][nf], afr[mf], bfr[nf]);
        }

        __syncwarp();
        if (lane == 0) MBAR_ARRIVE(barb + (4 + st) * 8);

        if (tid == 0 && kt + TG_STAGES < KT) {
            MBAR_WAIT(barb + (4 + st) * 8, ph);
            const uint32_t full = barb + st * 8;
            MBAR_EXPECT_TX(full, TG_STAGE_BYTES);
            const uint32_t sa = sbase + st * TG_STAGE_BYTES;
            tma2d(sa,         &tmA, (kt + TG_STAGES) * 64, mblk, full);
            tma2d(sa + 16384, &tmB, (kt + TG_STAGES) * 64, nblk, full);
        }
    }

#pragma unroll
    for (int nf = 0; nf < 8; nf++) {
        const int col = nblk + wn * 64 + nf * 8 + tig * 2;
        const float b0 = bias ? bias[col] : 0.f;
        const float b1 = bias ? bias[col + 1] : 0.f;
#pragma unroll
        for (int mf = 0; mf < 2; mf++) {
            const int row = mblk + wm * 32 + mf * 16 + gid;
            {
                float2 v = make_float2(acc[mf][nf][0] + b0, acc[mf][nf][1] + b1);
                *(float2*)(C + (size_t)row * N + col) = v;
            }
            {
                float2 v = make_float2(acc[mf][nf][2] + b0, acc[mf][nf][3] + b1);
                *(float2*)(C + (size_t)(row + 8) * N + col) = v;
            }
        }
    }
}

// ---------------- small tf32 GEMM (legacy mma): C = A @ B^T (+bias) ----------
#define SPITCH 136
__global__ __launch_bounds__(256, 2) void gemm_tf32_kernel(
    const float* __restrict__ A, const float* __restrict__ B,
    const float* __restrict__ bias, float* __restrict__ C,
    int M, int N, int K)
{
    __shared__ unsigned As[16][SPITCH];
    __shared__ unsigned Bs[16][SPITCH];

    const int tid  = threadIdx.x;
    const int warp = tid >> 5;
    const int lane = tid & 31;
    const int wm = warp & 1;
    const int wn = warp >> 1;
    const int gid = lane >> 2;
    const int tig = lane & 3;

    const int mblk = blockIdx.y * 128;
    const int nblk = blockIdx.x * 128;

    const int lr = tid >> 1;
    const int kc = (tid & 1) * 8;
    const int rowA = mblk + lr;
    const bool aval = rowA < M;
    const float* Ap = A + (size_t)(aval ? rowA : 0) * K + kc;
    const float* Bp = B + (size_t)(nblk + lr) * K + kc;

    float acc[4][4][4];
#pragma unroll
    for (int i = 0; i < 4; i++)
#pragma unroll
        for (int j = 0; j < 4; j++)
#pragma unroll
            for (int r = 0; r < 4; r++) acc[i][j][r] = 0.f;

    float4 av0 = aval ? *(const float4*)Ap : make_float4(0,0,0,0);
    float4 av1 = aval ? *(const float4*)(Ap + 4) : make_float4(0,0,0,0);
    float4 bv0 = *(const float4*)Bp;
    float4 bv1 = *(const float4*)(Bp + 4);
    Ap += 16; Bp += 16;

    for (int k0 = 0; k0 < K; k0 += 16) {
        As[kc + 0][lr] = f2tf32(av0.x); As[kc + 1][lr] = f2tf32(av0.y);
        As[kc + 2][lr] = f2tf32(av0.z); As[kc + 3][lr] = f2tf32(av0.w);
        As[kc + 4][lr] = f2tf32(av1.x); As[kc + 5][lr] = f2tf32(av1.y);
        As[kc + 6][lr] = f2tf32(av1.z); As[kc + 7][lr] = f2tf32(av1.w);
        Bs[kc + 0][lr] = f2tf32(bv0.x); Bs[kc + 1][lr] = f2tf32(bv0.y);
        Bs[kc + 2][lr] = f2tf32(bv0.z); Bs[kc + 3][lr] = f2tf32(bv0.w);
        Bs[kc + 4][lr] = f2tf32(bv1.x); Bs[kc + 5][lr] = f2tf32(bv1.y);
        Bs[kc + 6][lr] = f2tf32(bv1.z); Bs[kc + 7][lr] = f2tf32(bv1.w);
        __syncthreads();

        if (k0 + 16 < K) {
            av0 = aval ? *(const float4*)Ap : make_float4(0,0,0,0);
            av1 = aval ? *(const float4*)(Ap + 4) : make_float4(0,0,0,0);
            bv0 = *(const float4*)Bp;
            bv1 = *(const float4*)(Bp + 4);
            Ap += 16; Bp += 16;
        }

#pragma unroll
        for (int ks = 0; ks < 2; ks++) {
            const int kb = ks * 8;
            unsigned afr[4][4], bfr[4][2];
#pragma unroll
            for (int mt = 0; mt < 4; mt++) {
                const int mr = wm * 64 + mt * 16 + gid;
                afr[mt][0] = As[kb + tig][mr];
                afr[mt][1] = As[kb + tig][mr + 8];
                afr[mt][2] = As[kb + tig + 4][mr];
                afr[mt][3] = As[kb + tig + 4][mr + 8];
            }
#pragma unroll
            for (int nt = 0; nt < 4; nt++) {
                const int nc = wn * 32 + nt * 8 + gid;
                bfr[nt][0] = Bs[kb + tig][nc];
                bfr[nt][1] = Bs[kb + tig + 4][nc];
            }
#pragma unroll
            for (int mt = 0; mt < 4; mt++)
#pragma unroll
                for (int nt = 0; nt < 4; nt++)
                    mma_tf32(acc[mt][nt], afr[mt], bfr[nt]);
        }
        __syncthreads();
    }

#pragma unroll
    for (int nt = 0; nt < 4; nt++) {
        const int col = nblk + wn * 32 + nt * 8 + tig * 2;
        const float b0 = bias ? bias[col] : 0.f;
        const float b1 = bias ? bias[col + 1] : 0.f;
#pragma unroll
        for (int mt = 0; mt < 4; mt++) {
            const int row = mblk + wm * 64 + mt * 16 + gid;
            if (row < M) {
                float2 v = make_float2(acc[mt][nt][0] + b0, acc[mt][nt][1] + b1);
                *(float2*)(C + (size_t)row * N + col) = v;
            }
            if (row + 8 < M) {
                float2 v = make_float2(acc[mt][nt][2] + b0, acc[mt][nt][3] + b1);
                *(float2*)(C + (size_t)(row + 8) * N + col) = v;
            }
        }
    }
}

// ---------------- LayerNorm + ReLU (fp32 out) ----------------
__global__ __launch_bounds__(256) void ln_relu_kernel(
    const float* __restrict__ in, const float* __restrict__ g,
    const float* __restrict__ be, float* __restrict__ out, int C)
{
    __shared__ float red[256];
    const int row = blockIdx.x;
    const int tid = threadIdx.x;
    const float* rp = in + (size_t)row * C;
    float s = 0.f, sq = 0.f;
    for (int c = tid; c < C; c += 256) { float v = rp[c]; s += v; sq += v * v; }
    red[tid] = s; __syncthreads();
    for (int o = 128; o > 0; o >>= 1) { if (tid < o) red[tid] += red[tid + o]; __syncthreads(); }
    float mean = red[0] / (float)C;
    __syncthreads();
    red[tid] = sq; __syncthreads();
    for (int o = 128; o > 0; o >>= 1) { if (tid < o) red[tid] += red[tid + o]; __syncthreads(); }
    float var = red[0] / (float)C - mean * mean;
    float rs = rsqrtf(var + 1e-5f);
    float* op = out + (size_t)row * C;
    for (int c = tid; c < C; c += 256) {
        float v = (rp[c] - mean) * rs * g[c] + be[c];
        op[c] = fmaxf(v, 0.f);
    }
}

// ---------------- LayerNorm + ReLU (fp16 out) ----------------
__global__ __launch_bounds__(256) void ln_relu_f16_kernel(
    const float* __restrict__ in, const float* __restrict__ g,
    const float* __restrict__ be, __half* __restrict__ out, int C)
{
    __shared__ float red[256];
    const int row = blockIdx.x;
    const int tid = threadIdx.x;
    const float* rp = in + (size_t)row * C;
    float s = 0.f, sq = 0.f;
    for (int c = tid; c < C; c += 256) { float v = rp[c]; s += v; sq += v * v; }
    red[tid] = s; __syncthreads();
    for (int o = 128; o > 0; o >>= 1) { if (tid < o) red[tid] += red[tid + o]; __syncthreads(); }
    float mean = red[0] / (float)C;
    __syncthreads();
    red[tid] = sq; __syncthreads();
    for (int o = 128; o > 0; o >>= 1) { if (tid < o) red[tid] += red[tid + o]; __syncthreads(); }
    float var = red[0] / (float)C - mean * mean;
    float rs = rsqrtf(var + 1e-5f);
    __half* op = out + (size_t)row * C;
    for (int c = tid; c < C; c += 256) {
        float v = (rp[c] - mean) * rs * g[c] + be[c];
        op[c] = __float2half_rn(fmaxf(v, 0.f));
    }
}

// ---------------- concat [expanded(32); pos(128)] ----------------
__global__ __launch_bounds__(256) void concat_kernel(
    const float* __restrict__ e, const float* __restrict__ pos, float* __restrict__ o)
{
    int i = blockIdx.x * 256 + threadIdx.x;
    o[i] = (i < 32 * 1024) ? e[i] : pos[i - 32 * 1024];
}

// ---------------- pack h0 into exchange set 0 as (hi, lo*2048) half planes --------
__global__ __launch_bounds__(256) void pack_h0_kernel(
    const float* __restrict__ EXP, __half* __restrict__ HBh)
{
    int i = blockIdx.x * 256 + threadIdx.x;   // 128 blocks -> 32768 (b*1024+k)
    const float v = EXP[i];
    const __half hi = __float2half_rn(v);
    const __half lo = __float2half_rn((v - __half2float(hi)) * 2048.0f);
    HBh[i] = hi;            HBh[32768 + i] = lo;            // d=0
    HBh[65536 + i] = hi;    HBh[65536 + 32768 + i] = lo;    // d=1
}

// ---------------- persistent RNN layer (fp16 2-term split, 512 thr) ---------------
// 128 blocks: d = bid>>6, n0 = (bid&63)*16. 16 warps = 16-way k-split (64 k each).
// smem halves: Hh[32][1032] | Hl[32][1032] | Wh[16][1032] | Wl[16][1032].
// Red (32 KB fp32) aliases Hh.  Grid sync: per-direction 2-level tree barrier.
#define RNP 1032
#define RNN2_HL_OFF  (32 * RNP * 2)
#define RNN2_WH_OFF  (RNN2_HL_OFF * 2)
#define RNN2_WL_OFF  (RNN2_WH_OFF + 16 * RNP * 2)
#define RNN2_SMEM_BYTES (RNN2_WL_OFF + 16 * RNP * 2)

__device__ __forceinline__ unsigned ld_acquire_u32(unsigned* p) {
    unsigned v;
    asm volatile("ld.acquire.gpu.global.u32 %0, [%1];" : "=r"(v) : "l"(p) : "memory");
    return v;
}
__device__ __forceinline__ unsigned atom_add_acqrel(unsigned* p, unsigned v) {
    unsigned o;
    asm volatile("atom.acq_rel.gpu.global.add.u32 %0, [%1], %2;" : "=r"(o) : "l"(p), "r"(v) : "memory");
    return o;
}
__device__ __forceinline__ void st_relaxed_u32(unsigned* p, unsigned v) {
    asm volatile("st.relaxed.gpu.global.u32 [%0], %1;" :: "l"(p), "r"(v) : "memory");
}
__device__ __forceinline__ void st_release_u32(unsigned* p, unsigned v) {
    asm volatile("st.release.gpu.global.u32 [%0], %1;" :: "l"(p), "r"(v) : "memory");
}

__global__ __launch_bounds__(512, 1) void rnn_layer_kernel(
    const float* __restrict__ Whh, const float* __restrict__ gate,
    const float* __restrict__ bih, const float* __restrict__ bhh,
    __half* __restrict__ HBh, __half* __restrict__ Y, int layer)
{
    extern __shared__ char sm2[];
    __half* Hh = (__half*)sm2;
    __half* Hl = (__half*)(sm2 + RNN2_HL_OFF);
    __half* Wh = (__half*)(sm2 + RNN2_WH_OFF);
    __half* Wl = (__half*)(sm2 + RNN2_WL_OFF);

    const int tid  = threadIdx.x;
    const int bid  = blockIdx.x;
    const int d    = bid >> 6;
    const int nb   = bid & 63;
    const int n0   = nb * 16;
    const int kq   = tid >> 5;        // 0..15, k-slice [kq*64, +64)
    const int lane = tid & 31;
    const int gid  = lane >> 2;
    const int tig  = lane & 3;

    // prologue: split W into hi fp16 + lo fp16 (x2048), layout [n][k]
    for (int i = tid; i < 16384; i += 512) {
        const int n = i >> 10, k = i & 1023;
        const float w = Whh[(size_t)(d * 1024 + n0 + n) * 1024 + k];
        const __half hi = __float2half_rn(w);
        Wh[n * RNP + k] = hi;
        Wl[n * RNP + k] = __float2half_rn((w - __half2float(hi)) * 2048.0f);
    }
    __syncthreads();

    // step-invariant epilogue terms
    const int eb   = tid >> 4;
    const int encl = n0 + (tid & 15);
    const int ecol = d * 1024 + encl;
    const float bb = bih[ecol] + bhh[ecol];
    float gB = 0.f;
    if (layer == 0) gB = gate[(size_t)eb * 2048 + ecol];

    // tree barrier pointers
    const int leafid = nb >> 3;                        // 0..7
    unsigned* leafp  = &g_leaf[(d * 8 + leafid) * 32];
    unsigned* rootp  = &g_root[d * 32];
    unsigned* sensep = &g_sense[d * 32];
    unsigned bar_sense = 0;

    for (int s = 1; s <= T_LEN; s++) {
        const int t = d ? (T_LEN - s) : (s - 1);

        float gT;
        if (layer == 0) gT = gate[(size_t)(32 + t) * 2048 + ecol];
        else            gT = gate[(size_t)(t * 32 + eb) * 2048 + ecol];

        // ---- each warp copies its 64-wide k-slice of both h planes ----
        const __half* srcH = HBh + ((s - 1) & 1) * 131072 + d * 65536;
        const __half* srcL = srcH + 32768;
        for (int j = lane; j < 256; j += 32) {
            const int b = j >> 3, u = j & 7;     // 8 uint4 per 64-half row slice
            const int go = b * 1024 + kq * 64 + u * 8;
            const int so = b * RNP + kq * 64 + u * 8;
            *(uint4*)&Hh[so] = *(const uint4*)&srcH[go];
            *(uint4*)&Hl[so] = *(const uint4*)&srcL[go];
        }
        __syncwarp();

        // ---- fp16 2-term mma over k-slice [kq*64, +64) ----
        float acc1[2][2][4], acc2[2][2][4];
#pragma unroll
        for (int i = 0; i < 2; i++)
#pragma unroll
            for (int j = 0; j < 2; j++)
#pragma unroll
                for (int r = 0; r < 4; r++) { acc1[i][j][r] = 0.f; acc2[i][j][r] = 0.f; }

#pragma unroll
        for (int kf = 0; kf < 4; kf++) {
            const int kk = kq * 64 + kf * 16;
            unsigned ahi[2][4], alo[2][4];
#pragma unroll
            for (int mt = 0; mt < 2; mt++) {
                const int r0 = (mt * 16 + gid) * RNP + kk + tig * 2;
                const int r1 = (mt * 16 + gid + 8) * RNP + kk + tig * 2;
                ahi[mt][0] = *(const unsigned*)&Hh[r0];
                ahi[mt][1] = *(const unsigned*)&Hh[r1];
                ahi[mt][2] = *(const unsigned*)&Hh[r0 + 8];
                ahi[mt][3] = *(const unsigned*)&Hh[r1 + 8];
                alo[mt][0] = *(const unsigned*)&Hl[r0];
                alo[mt][1] = *(const unsigned*)&Hl[r1];
                alo[mt][2] = *(const unsigned*)&Hl[r0 + 8];
                alo[mt][3] = *(const unsigned*)&Hl[r1 + 8];
            }
            unsigned bhi[2][2], blo[2][2];
#pragma unroll
            for (int nt = 0; nt < 2; nt++) {
                const int c0 = (nt * 8 + gid) * RNP + kk + tig * 2;
                bhi[nt][0] = *(const unsigned*)&Wh[c0];
                bhi[nt][1] = *(const unsigned*)&Wh[c0 + 8];
                blo[nt][0] = *(const unsigned*)&Wl[c0];
                blo[nt][1] = *(const unsigned*)&Wl[c0 + 8];
            }
#pragma unroll
            for (int mt = 0; mt < 2; mt++)
#pragma unroll
                for (int nt = 0; nt < 2; nt++) {
                    mma_f16(acc1[mt][nt], ahi[mt], bhi[nt]);   // hi*hi
                    mma_f16(acc2[mt][nt], alo[mt], bhi[nt]);   // lo*hi (x2048)
                    mma_f16(acc2[mt][nt], ahi[mt], blo[nt]);   // hi*lo (x2048)
                }
        }

        // ---- cross-warp k-reduction via Red (fp32, aliases Hh) ----
        __syncthreads();
        float* Red = (float*)Hh;   // Red[kq*512 + b*16 + n], 8192 floats = 32KB
#pragma unroll
        for (int mt = 0; mt < 2; mt++)
#pragma unroll
            for (int nt = 0; nt < 2; nt++)
#pragma unroll
                for (int r = 0; r < 4; r++) {
                    const int b = mt * 16 + gid + ((r >> 1) << 3);
                    const int n = nt * 8 + tig * 2 + (r & 1);
                    Red[kq * 512 + b * 16 + n] =
                        acc1[mt][nt][r] + acc2[mt][nt][r] * (1.0f / 2048.0f);
                }
        __syncthreads();

        // ---- epilogue: one output per thread ----
        {
            float v = 0.f;
#pragma unroll
            for (int kq2 = 0; kq2 < 16; kq2++) v += Red[kq2 * 512 + tid];
            const float hnew = fmaxf(v + gB + gT + bb, 0.f);
            const __half hhi = __float2half_rn(hnew);
            const __half hlo = __float2half_rn((hnew - __half2float(hhi)) * 2048.0f);
            __half* dstH = HBh + (s & 1) * 131072 + d * 65536;
            dstH[eb * 1024 + encl] = hhi;
            dstH[32768 + eb * 1024 + encl] = hlo;
            const int row = layer ? (eb * 128 + t) : (t * 32 + eb);
            Y[(size_t)row * 2048 + ecol] = hhi;
        }

        // ---- per-direction grid barrier: 2-level tree (8 leaves x 8) ----
        __syncthreads();
        if (tid == 0) {
            const unsigned target = bar_sense ^ 1;
            unsigned lold = atom_add_acqrel(leafp, 1);
            if (lold == 7) {
                st_relaxed_u32(leafp, 0);                 // unique last in leaf
                unsigned rold = atom_add_acqrel(rootp, 1);
                if (rold == 7) {
                    st_relaxed_u32(rootp, 0);             // unique last at root
                    st_release_u32(sensep, target);
                } else {
                    while (ld_acquire_u32(sensep) != target) { }
                }
            } else {
                while (ld_acquire_u32(sensep) != target) { }
            }
        }
        bar_sense ^= 1;
        __syncthreads();
    }
}

// ---------------- launch helpers ----------------
static inline void gemm_small(const float* A, const float* B, const float* bias,
                              float* C, int M, int N, int K)
{
    dim3 grid(N / 128, (M + 127) / 128);
    gemm_tf32_kernel<<<grid, 256>>>(A, B, bias, C, M, N, K);
}

typedef CUresult (CUDAAPI *PFN_encodeTiled)(
    CUtensorMap*, CUtensorMapDataType, cuuint32_t, void*,
    const cuuint64_t*, const cuuint64_t*, const cuuint32_t*, const cuuint32_t*,
    CUtensorMapInterleave, CUtensorMapSwizzle, CUtensorMapL2promotion,
    CUtensorMapFloatOOBfill);

static inline CUtensorMap make_map2d_f16(PFN_encodeTiled enc, const void* ptr,
                                         int rows, int K, int boxRows)
{
    CUtensorMap m{};
    cuuint64_t dims[2]    = {(cuuint64_t)K, (cuuint64_t)rows};
    cuuint64_t strides[1] = {(cuuint64_t)K * 2};
    cuuint32_t box[2]     = {64u, (cuuint32_t)boxRows};
    cuuint32_t es[2]      = {1u, 1u};
    enc(&m, CU_TENSOR_MAP_DATA_TYPE_UINT16, 2, (void*)ptr,
        dims, strides, box, es,
        CU_TENSOR_MAP_INTERLEAVE_NONE, CU_TENSOR_MAP_SWIZZLE_128B,
        CU_TENSOR_MAP_L2_PROMOTION_L2_128B, CU_TENSOR_MAP_FLOAT_OOB_FILL_NONE);
    return m;
}

extern "C" void kernel_launch(void* const* d_in, const int* in_sizes, int n_in,
                              void* d_out, int out_size)
{
    (void)in_sizes; (void)n_in; (void)out_size;
    const float* x     = (const float*)d_in[0];
    const float* W_exp = (const float*)d_in[1];
    const float* b_exp = (const float*)d_in[2];
    const float* g1    = (const float*)d_in[3];
    const float* be1   = (const float*)d_in[4];
    const float* pos   = (const float*)d_in[5];
    const float* Wih0  = (const float*)d_in[6];
    const float* Whh0  = (const float*)d_in[7];
    const float* bih0  = (const float*)d_in[8];
    const float* bhh0  = (const float*)d_in[9];
    const float* Wih1  = (const float*)d_in[10];
    const float* Whh1  = (const float*)d_in[11];
    const float* bih1  = (const float*)d_in[12];
    const float* bhh1  = (const float*)d_in[13];
    const float* Wp1   = (const float*)d_in[14];
    const float* bp1   = (const float*)d_in[15];
    const float* g2    = (const float*)d_in[16];
    const float* be2   = (const float*)d_in[17];
    const float* Wp2   = (const float*)d_in[18];
    const float* bp2   = (const float*)d_in[19];
    float* out = (float*)d_out;

    float* S = nullptr;
    cudaGetSymbolAddress((void**)&S, g_scratch);

    float*  PRE   = S + OFF_PRE;
    float*  EXP   = S + OFF_EXP;
    float*  A0IN  = S + OFF_A0IN;
    float*  C0    = S + OFF_C0;
    __half* HBh   = (__half*)(S + OFF_HB);
    __half* X1H   = (__half*)(S + OFF_X1H);
    float*  G1    = S + OFF_G1;
    __half* OUT2H = (__half*)(S + OFF_OUT2H);
    float*  PROJ  = S + OFF_PROJ;
    __half* HEH   = (__half*)(S + OFF_HEH);
    __half* WIH1H = (__half*)(S + OFF_WIH1H);
    __half* WP1H  = (__half*)(S + OFF_WP1H);
    __half* WP2H  = (__half*)(S + OFF_WP2H);

    PFN_encodeTiled enc = nullptr;
    cudaGetDriverEntryPoint("cuTensorMapEncodeTiled", (void**)&enc, cudaEnableDefault);

    CUtensorMap tmA_G1  = make_map2d_f16(enc, X1H,   4096,  2048, 128);
    CUtensorMap tmB_G1  = make_map2d_f16(enc, WIH1H, 2048,  2048, 256);
    CUtensorMap tmA_PRJ = make_map2d_f16(enc, OUT2H, 4096,  2048, 128);
    CUtensorMap tmB_PRJ = make_map2d_f16(enc, WP1H,  512,   2048, 256);
    CUtensorMap tmA_LOG = make_map2d_f16(enc, HEH,   4096,  512,  128);
    CUtensorMap tmB_LOG = make_map2d_f16(enc, WP2H,  32000, 512,  256);

    cudaFuncSetAttribute(rnn_layer_kernel,
                         cudaFuncAttributeMaxDynamicSharedMemorySize, RNN2_SMEM_BYTES);
    cudaFuncSetAttribute(gemm_tma_f16_kernel,
                         cudaFuncAttributeMaxDynamicSharedMemorySize, TG_SMEM_BYTES);

    // 0) pre-convert weights to fp16
    tohalf_kernel<<<512, 256>>>(Wih1, (__half2*)WIH1H, 2 * 1024 * 2048 / 4);
    tohalf_kernel<<<512, 256>>>(Wp1,  (__half2*)WP1H,  512 * 2048 / 4);
    tohalf_kernel<<<512, 256>>>(Wp2,  (__half2*)WP2H,  32000 * 512 / 4);

    // 1) expand (proven tf32 tile) + LN/ReLU
    gemm_small(x, W_exp, b_exp, PRE, 32, 1024, 512);
    ln_relu_kernel<<<32, 256>>>(PRE, g1, be1, EXP, 1024);

    // 2) layer-0 gate factors
    concat_kernel<<<640, 256>>>(EXP, pos, A0IN);
    gemm_small(A0IN, Wih0, nullptr, C0, 160, 2048, 1024);

    // 3) layer-0 recurrence (persistent, fp16 2-term), writes X1 as fp16
    pack_h0_kernel<<<128, 256>>>(EXP, HBh);
    rnn_layer_kernel<<<128, 512, RNN2_SMEM_BYTES>>>(Whh0, C0, bih0, bhh0, HBh, X1H, 0);

    // 4) layer-1 gates (fp16 TMA GEMM): G1[4096,2048] fp32 out
    {
        dim3 grid(2048 / 256, 4096 / 128);
        gemm_tma_f16_kernel<<<grid, 512, TG_SMEM_BYTES>>>(tmA_G1, tmB_G1, nullptr, G1, 2048, 2048);
    }

    // 5) layer-1 recurrence (persistent, fp16 2-term), writes OUT2 as fp16
    pack_h0_kernel<<<128, 256>>>(EXP, HBh);
    rnn_layer_kernel<<<128, 512, RNN2_SMEM_BYTES>>>(Whh1, G1, bih1, bhh1, HBh, OUT2H, 1);

    // 6) projection head (fp16 TMA GEMM) + LN+ReLU -> fp16
    {
        dim3 grid(512 / 256, 4096 / 128);
        gemm_tma_f16_kernel<<<grid, 512, TG_SMEM_BYTES>>>(tmA_PRJ, tmB_PRJ, bp1, PROJ, 512, 2048);
    }
    ln_relu_f16_kernel<<<4096, 256>>>(PROJ, g2, be2, HEH, 512);

    // 7) logits (fp16 TMA GEMM)
    {
        dim3 grid(32000 / 256, 4096 / 128);
        gemm_tma_f16_kernel<<<grid, 512, TG_SMEM_BYTES>>>(tmA_LOG, tmB_LOG, bp2, out, 32000, 512);
    }
}

// round 17
// speedup vs baseline: 1.1191x; 1.1191x over previous
#include <cuda_runtime.h>
#include <cuda.h>
#include <cuda_fp16.h>
#include <cstdint>

#define T_LEN 128

// ---------------- scratch layout (float units) ----------------
#define OFF_PRE   0                                   // [32][1024] f32
#define OFF_EXP   (OFF_PRE  + 32*1024)                // [32][1024] f32
#define OFF_A0INH (OFF_EXP  + 32*1024)                // half[160][1024]
#define OFF_C0    (OFF_A0INH + 80*1024)               // f32 [256][2048] (rows >=160 dead)
#define OFF_HB    (OFF_C0   + 256*2048)               // half: 2 sets x [2 d][2 pl][32][1024]
#define OFF_X1H   (OFF_HB   + 2*2*32*1024)            // half[4096][2048]
#define OFF_G1    (OFF_X1H  + 4096*1024)              // f32 [4096][2048]
#define OFF_OUT2H (OFF_G1   + 4096*2048)              // half[4096][2048]
#define OFF_PROJ  (OFF_OUT2H + 4096*1024)             // f32 [4096][512]
#define OFF_HEH   (OFF_PROJ + 4096*512)               // half[4096][512]
#define OFF_WIH1H (OFF_HEH  + 4096*256)               // half[2048][2048]
#define OFF_WP1H  (OFF_WIH1H + 2048*1024)             // half[512][2048]
#define OFF_WP2H  (OFF_WP1H  + 512*1024)              // half[32000][512]
#define OFF_WIH0H (OFF_WP2H + 32000*256)              // half[2048][1024]
#define SCRATCH_TOTAL (OFF_WIH0H + 2048*512)

__device__ __align__(1024) float g_scratch[SCRATCH_TOTAL];
__device__ unsigned g_bar_count2[2];
__device__ unsigned g_bar_sense2[2];

// ---------------- helpers ----------------
__device__ __forceinline__ unsigned f2tf32(float f) {
    unsigned u;
    asm("cvt.rna.tf32.f32 %0, %1;" : "=r"(u) : "f"(f));
    return u;
}

__device__ __forceinline__ void mma_tf32(float c[4], const unsigned a[4], const unsigned b[2]) {
    asm volatile(
        "mma.sync.aligned.m16n8k8.row.col.f32.tf32.tf32.f32 "
        "{%0,%1,%2,%3}, {%4,%5,%6,%7}, {%8,%9}, {%0,%1,%2,%3};"
        : "+f"(c[0]), "+f"(c[1]), "+f"(c[2]), "+f"(c[3])
        : "r"(a[0]), "r"(a[1]), "r"(a[2]), "r"(a[3]), "r"(b[0]), "r"(b[1]));
}

__device__ __forceinline__ void mma_f16(float c[4], const unsigned a[4], const unsigned b[2]) {
    asm volatile(
        "mma.sync.aligned.m16n8k16.row.col.f32.f16.f16.f32 "
        "{%0,%1,%2,%3}, {%4,%5,%6,%7}, {%8,%9}, {%0,%1,%2,%3};"
        : "+f"(c[0]), "+f"(c[1]), "+f"(c[2]), "+f"(c[3])
        : "r"(a[0]), "r"(a[1]), "r"(a[2]), "r"(a[3]), "r"(b[0]), "r"(b[1]));
}

// ---------------- fp32 -> fp16 convert ----------------
__global__ __launch_bounds__(256) void tohalf_kernel(
    const float* __restrict__ in, __half2* __restrict__ out, int n4)
{
    for (int i = blockIdx.x * 256 + threadIdx.x; i < n4; i += gridDim.x * 256) {
        float4 v = ((const float4*)in)[i];
        out[2 * i]     = __floats2half2_rn(v.x, v.y);
        out[2 * i + 1] = __floats2half2_rn(v.z, v.w);
    }
}

// =================== TMA-fed fp16 GEMM (mma.sync f16, f32 accum) ===================
#define TG_STAGES 4
#define TG_STAGE_BYTES 49152                   // A 128*128B + B 256*128B
#define TG_SMEM_BYTES  (1024 + TG_STAGES * TG_STAGE_BYTES)

__device__ __forceinline__ uint32_t smem_u32(const void* p) {
    return (uint32_t)__cvta_generic_to_shared((void*)p);
}
__device__ __forceinline__ void tma2d(uint32_t sdst, const CUtensorMap* tm,
                                      int x, int y, uint32_t bar) {
    asm volatile(
        "cp.async.bulk.tensor.2d.shared::cta.global.tile.mbarrier::complete_tx::bytes "
        "[%0], [%1, {%2, %3}], [%4];"
        :: "r"(sdst), "l"(tm), "r"(x), "r"(y), "r"(bar) : "memory");
}
#define MBAR_INIT(a, c) \
    asm volatile("mbarrier.init.shared.b64 [%0], %1;" :: "r"(a), "r"(c) : "memory")
#define MBAR_EXPECT_TX(a, b) \
    asm volatile("mbarrier.arrive.expect_tx.shared.b64 _, [%0], %1;" :: "r"(a), "r"(b) : "memory")
#define MBAR_ARRIVE(a) \
    asm volatile("mbarrier.arrive.shared.b64 _, [%0];" :: "r"(a) : "memory")
#define MBAR_WAIT(a, ph) do { \
    uint32_t _d_; \
    asm volatile("{\n\t.reg .pred p;\n\tmbarrier.try_wait.parity.acquire.cta.shared::cta.b64 p, [%1], %2;\n\tselp.b32 %0, 1, 0, p;\n\t}" \
        : "=r"(_d_) : "r"(a), "r"(ph) : "memory"); \
    while (!_d_) { \
        asm volatile("{\n\t.reg .pred p;\n\tmbarrier.try_wait.parity.acquire.cta.shared::cta.b64 p, [%1], %2, 0x989680;\n\tselp.b32 %0, 1, 0, p;\n\t}" \
            : "=r"(_d_) : "r"(a), "r"(ph) : "memory"); \
    } \
} while (0)

__global__ __launch_bounds__(512, 1) void gemm_tma_f16_kernel(
    const __grid_constant__ CUtensorMap tmA,
    const __grid_constant__ CUtensorMap tmB,
    const float* __restrict__ bias, float* __restrict__ C,
    int N, int K)
{
    extern __shared__ char dsm[];
    __shared__ __align__(8) unsigned long long bars[8];  // full[4], empty[4]

    const int tid  = threadIdx.x;
    const int warp = tid >> 5;
    const int lane = tid & 31;
    const int wm   = warp & 3;
    const int wn   = warp >> 2;
    const int gid  = lane >> 2;
    const int tig  = lane & 3;
    const int mblk = blockIdx.y * 128;
    const int nblk = blockIdx.x * 256;
    const int KT   = K / 64;

    const uint32_t raw   = smem_u32(dsm);
    const uint32_t sbase = (raw + 1023) & ~1023u;
    char* tile0 = dsm + (sbase - raw);
    const uint32_t barb = smem_u32(bars);

    if (tid == 0) {
        for (int i = 0; i < 4; i++) MBAR_INIT(barb + i * 8, 1);
        for (int i = 4; i < 8; i++) MBAR_INIT(barb + i * 8, 16);
    }
    __syncthreads();

    if (tid == 0) {
        const int pre = KT < TG_STAGES ? KT : TG_STAGES;
        for (int st = 0; st < pre; st++) {
            const uint32_t full = barb + st * 8;
            MBAR_EXPECT_TX(full, TG_STAGE_BYTES);
            const uint32_t sa = sbase + st * TG_STAGE_BYTES;
            tma2d(sa,         &tmA, st * 64, mblk, full);
            tma2d(sa + 16384, &tmB, st * 64, nblk, full);
        }
    }

    float acc[2][8][4];
#pragma unroll
    for (int i = 0; i < 2; i++)
#pragma unroll
        for (int j = 0; j < 8; j++)
#pragma unroll
            for (int r = 0; r < 4; r++) acc[i][j][r] = 0.f;

    const uint32_t xorv = (uint32_t)gid << 4;

    for (int kt = 0; kt < KT; kt++) {
        const int st = kt & 3;
        const uint32_t ph = (kt >> 2) & 1;
        MBAR_WAIT(barb + st * 8, ph);

        const char* As = tile0 + st * TG_STAGE_BYTES;
        const char* Bs = As + 16384;

#pragma unroll
        for (int ks = 0; ks < 4; ks++) {
            const uint32_t c4a = (uint32_t)(ks * 32 + tig * 4) ^ xorv;
            const uint32_t c4b = (uint32_t)(ks * 32 + tig * 4 + 16) ^ xorv;
            unsigned afr[2][4], bfr[8][2];
#pragma unroll
            for (int mf = 0; mf < 2; mf++) {
                const int r0 = wm * 32 + mf * 16 + gid;
                afr[mf][0] = *(const unsigned*)(As + r0 * 128 + c4a);
                afr[mf][1] = *(const unsigned*)(As + (r0 + 8) * 128 + c4a);
                afr[mf][2] = *(const unsigned*)(As + r0 * 128 + c4b);
                afr[mf][3] = *(const unsigned*)(As + (r0 + 8) * 128 + c4b);
            }
#pragma unroll
            for (int nf = 0; nf < 8; nf++) {
                const int nc = wn * 64 + nf * 8 + gid;
                bfr[nf][0] = *(const unsigned*)(Bs + nc * 128 + c4a);
                bfr[nf][1] = *(const unsigned*)(Bs + nc * 128 + c4b);
            }
#pragma unroll
            for (int mf = 0; mf < 2; mf++)
#pragma unroll
                for (int nf = 0; nf < 8; nf++)
                    mma_f16(acc[mf][nf], afr[mf], bfr[nf]);
        }

        __syncwarp();
        if (lane == 0) MBAR_ARRIVE(barb + (4 + st) * 8);

        if (tid == 0 && kt + TG_STAGES < KT) {
            MBAR_WAIT(barb + (4 + st) * 8, ph);
            const uint32_t full = barb + st * 8;
            MBAR_EXPECT_TX(full, TG_STAGE_BYTES);
            const uint32_t sa = sbase + st * TG_STAGE_BYTES;
            tma2d(sa,         &tmA, (kt + TG_STAGES) * 64, mblk, full);
            tma2d(sa + 16384, &tmB, (kt + TG_STAGES) * 64, nblk, full);
        }
    }

#pragma unroll
    for (int nf = 0; nf < 8; nf++) {
        const int col = nblk + wn * 64 + nf * 8 + tig * 2;
        const float b0 = bias ? bias[col] : 0.f;
        const float b1 = bias ? bias[col + 1] : 0.f;
#pragma unroll
        for (int mf = 0; mf < 2; mf++) {
            const int row = mblk + wm * 32 + mf * 16 + gid;
            {
                float2 v = make_float2(acc[mf][nf][0] + b0, acc[mf][nf][1] + b1);
                *(float2*)(C + (size_t)row * N + col) = v;
            }
            {
                float2 v = make_float2(acc[mf][nf][2] + b0, acc[mf][nf][3] + b1);
                *(float2*)(C + (size_t)(row + 8) * N + col) = v;
            }
        }
    }
}

// ---------------- small tf32 GEMM (legacy mma): C = A @ B^T (+bias) ----------
#define SPITCH 136
__global__ __launch_bounds__(256, 2) void gemm_tf32_kernel(
    const float* __restrict__ A, const float* __restrict__ B,
    const float* __restrict__ bias, float* __restrict__ C,
    int M, int N, int K)
{
    __shared__ unsigned As[16][SPITCH];
    __shared__ unsigned Bs[16][SPITCH];

    const int tid  = threadIdx.x;
    const int warp = tid >> 5;
    const int lane = tid & 31;
    const int wm = warp & 1;
    const int wn = warp >> 1;
    const int gid = lane >> 2;
    const int tig = lane & 3;

    const int mblk = blockIdx.y * 128;
    const int nblk = blockIdx.x * 128;

    const int lr = tid >> 1;
    const int kc = (tid & 1) * 8;
    const int rowA = mblk + lr;
    const bool aval = rowA < M;
    const float* Ap = A + (size_t)(aval ? rowA : 0) * K + kc;
    const float* Bp = B + (size_t)(nblk + lr) * K + kc;

    float acc[4][4][4];
#pragma unroll
    for (int i = 0; i < 4; i++)
#pragma unroll
        for (int j = 0; j < 4; j++)
#pragma unroll
            for (int r = 0; r < 4; r++) acc[i][j][r] = 0.f;

    float4 av0 = aval ? *(const float4*)Ap : make_float4(0,0,0,0);
    float4 av1 = aval ? *(const float4*)(Ap + 4) : make_float4(0,0,0,0);
    float4 bv0 = *(const float4*)Bp;
    float4 bv1 = *(const float4*)(Bp + 4);
    Ap += 16; Bp += 16;

    for (int k0 = 0; k0 < K; k0 += 16) {
        As[kc + 0][lr] = f2tf32(av0.x); As[kc + 1][lr] = f2tf32(av0.y);
        As[kc + 2][lr] = f2tf32(av0.z); As[kc + 3][lr] = f2tf32(av0.w);
        As[kc + 4][lr] = f2tf32(av1.x); As[kc + 5][lr] = f2tf32(av1.y);
        As[kc + 6][lr] = f2tf32(av1.z); As[kc + 7][lr] = f2tf32(av1.w);
        Bs[kc + 0][lr] = f2tf32(bv0.x); Bs[kc + 1][lr] = f2tf32(bv0.y);
        Bs[kc + 2][lr] = f2tf32(bv0.z); Bs[kc + 3][lr] = f2tf32(bv0.w);
        Bs[kc + 4][lr] = f2tf32(bv1.x); Bs[kc + 5][lr] = f2tf32(bv1.y);
        Bs[kc + 6][lr] = f2tf32(bv1.z); Bs[kc + 7][lr] = f2tf32(bv1.w);
        __syncthreads();

        if (k0 + 16 < K) {
            av0 = aval ? *(const float4*)Ap : make_float4(0,0,0,0);
            av1 = aval ? *(const float4*)(Ap + 4) : make_float4(0,0,0,0);
            bv0 = *(const float4*)Bp;
            bv1 = *(const float4*)(Bp + 4);
            Ap += 16; Bp += 16;
        }

#pragma unroll
        for (int ks = 0; ks < 2; ks++) {
            const int kb = ks * 8;
            unsigned afr[4][4], bfr[4][2];
#pragma unroll
            for (int mt = 0; mt < 4; mt++) {
                const int mr = wm * 64 + mt * 16 + gid;
                afr[mt][0] = As[kb + tig][mr];
                afr[mt][1] = As[kb + tig][mr + 8];
                afr[mt][2] = As[kb + tig + 4][mr];
                afr[mt][3] = As[kb + tig + 4][mr + 8];
            }
#pragma unroll
            for (int nt = 0; nt < 4; nt++) {
                const int nc = wn * 32 + nt * 8 + gid;
                bfr[nt][0] = Bs[kb + tig][nc];
                bfr[nt][1] = Bs[kb + tig + 4][nc];
            }
#pragma unroll
            for (int mt = 0; mt < 4; mt++)
#pragma unroll
                for (int nt = 0; nt < 4; nt++)
                    mma_tf32(acc[mt][nt], afr[mt], bfr[nt]);
        }
        __syncthreads();
    }

#pragma unroll
    for (int nt = 0; nt < 4; nt++) {
        const int col = nblk + wn * 32 + nt * 8 + tig * 2;
        const float b0 = bias ? bias[col] : 0.f;
        const float b1 = bias ? bias[col + 1] : 0.f;
#pragma unroll
        for (int mt = 0; mt < 4; mt++) {
            const int row = mblk + wm * 64 + mt * 16 + gid;
            if (row < M) {
                float2 v = make_float2(acc[mt][nt][0] + b0, acc[mt][nt][1] + b1);
                *(float2*)(C + (size_t)row * N + col) = v;
            }
            if (row + 8 < M) {
                float2 v = make_float2(acc[mt][nt][2] + b0, acc[mt][nt][3] + b1);
                *(float2*)(C + (size_t)(row + 8) * N + col) = v;
            }
        }
    }
}

// ---------------- LayerNorm + ReLU (fp32 out) ----------------
__global__ __launch_bounds__(256) void ln_relu_kernel(
    const float* __restrict__ in, const float* __restrict__ g,
    const float* __restrict__ be, float* __restrict__ out, int C)
{
    __shared__ float red[256];
    const int row = blockIdx.x;
    const int tid = threadIdx.x;
    const float* rp = in + (size_t)row * C;
    float s = 0.f, sq = 0.f;
    for (int c = tid; c < C; c += 256) { float v = rp[c]; s += v; sq += v * v; }
    red[tid] = s; __syncthreads();
    for (int o = 128; o > 0; o >>= 1) { if (tid < o) red[tid] += red[tid + o]; __syncthreads(); }
    float mean = red[0] / (float)C;
    __syncthreads();
    red[tid] = sq; __syncthreads();
    for (int o = 128; o > 0; o >>= 1) { if (tid < o) red[tid] += red[tid + o]; __syncthreads(); }
    float var = red[0] / (float)C - mean * mean;
    float rs = rsqrtf(var + 1e-5f);
    float* op = out + (size_t)row * C;
    for (int c = tid; c < C; c += 256) {
        float v = (rp[c] - mean) * rs * g[c] + be[c];
        op[c] = fmaxf(v, 0.f);
    }
}

// ---------------- LayerNorm + ReLU (fp16 out) ----------------
__global__ __launch_bounds__(256) void ln_relu_f16_kernel(
    const float* __restrict__ in, const float* __restrict__ g,
    const float* __restrict__ be, __half* __restrict__ out, int C)
{
    __shared__ float red[256];
    const int row = blockIdx.x;
    const int tid = threadIdx.x;
    const float* rp = in + (size_t)row * C;
    float s = 0.f, sq = 0.f;
    for (int c = tid; c < C; c += 256) { float v = rp[c]; s += v; sq += v * v; }
    red[tid] = s; __syncthreads();
    for (int o = 128; o > 0; o >>= 1) { if (tid < o) red[tid] += red[tid + o]; __syncthreads(); }
    float mean = red[0] / (float)C;
    __syncthreads();
    red[tid] = sq; __syncthreads();
    for (int o = 128; o > 0; o >>= 1) { if (tid < o) red[tid] += red[tid + o]; __syncthreads(); }
    float var = red[0] / (float)C - mean * mean;
    float rs = rsqrtf(var + 1e-5f);
    __half* op = out + (size_t)row * C;
    for (int c = tid; c < C; c += 256) {
        float v = (rp[c] - mean) * rs * g[c] + be[c];
        op[c] = __float2half_rn(fmaxf(v, 0.f));
    }
}

// ---------------- concat -> fp16 [expanded(32); pos(128)] ----------------
__global__ __launch_bounds__(256) void concat_f16_kernel(
    const float* __restrict__ e, const float* __restrict__ pos, __half* __restrict__ o)
{
    int i = blockIdx.x * 256 + threadIdx.x;   // 640 blocks -> 160*1024 exact
    const float v = (i < 32 * 1024) ? e[i] : pos[i - 32 * 1024];
    o[i] = __float2half_rn(v);
}

// ---------------- pack h0 into exchange set 0 as (hi, lo*2048) half planes --------
__global__ __launch_bounds__(256) void pack_h0_kernel(
    const float* __restrict__ EXP, __half* __restrict__ HBh)
{
    int i = blockIdx.x * 256 + threadIdx.x;   // 128 blocks -> 32768 (b*1024+k)
    const float v = EXP[i];
    const __half hi = __float2half_rn(v);
    const __half lo = __float2half_rn((v - __half2float(hi)) * 2048.0f);
    HBh[i] = hi;            HBh[32768 + i] = lo;            // d=0
    HBh[65536 + i] = hi;    HBh[65536 + 32768 + i] = lo;    // d=1
}

// ---------------- persistent RNN layer (fp16 2-term split, 512 thr) ---------------
// 128 blocks: d = bid>>6, n0 = (bid&63)*16. 16 warps = 16-way k-split (64 k each).
// smem halves: Hh[32][1032] | Hl[32][1032] | Wh[16][1032] | Wl[16][1032].
// Red (32 KB fp32) aliases Hh.  Grid sync: per-direction flat atomic sense-reversal.
#define RNP 1032
#define RNN2_HL_OFF  (32 * RNP * 2)
#define RNN2_WH_OFF  (RNN2_HL_OFF * 2)
#define RNN2_WL_OFF  (RNN2_WH_OFF + 16 * RNP * 2)
#define RNN2_SMEM_BYTES (RNN2_WL_OFF + 16 * RNP * 2)

__device__ __forceinline__ unsigned ld_acquire_u32(unsigned* p) {
    unsigned v;
    asm volatile("ld.acquire.gpu.global.u32 %0, [%1];" : "=r"(v) : "l"(p) : "memory");
    return v;
}
__device__ __forceinline__ unsigned atom_add_acqrel(unsigned* p, unsigned v) {
    unsigned o;
    asm volatile("atom.acq_rel.gpu.global.add.u32 %0, [%1], %2;" : "=r"(o) : "l"(p), "r"(v) : "memory");
    return o;
}
__device__ __forceinline__ void st_relaxed_u32(unsigned* p, unsigned v) {
    asm volatile("st.relaxed.gpu.global.u32 [%0], %1;" :: "l"(p), "r"(v) : "memory");
}
__device__ __forceinline__ void st_release_u32(unsigned* p, unsigned v) {
    asm volatile("st.release.gpu.global.u32 [%0], %1;" :: "l"(p), "r"(v) : "memory");
}

__global__ __launch_bounds__(512, 1) void rnn_layer_kernel(
    const float* __restrict__ Whh, const float* __restrict__ gate,
    const float* __restrict__ bih, const float* __restrict__ bhh,
    __half* __restrict__ HBh, __half* __restrict__ Y, int layer)
{
    extern __shared__ char sm2[];
    __half* Hh = (__half*)sm2;
    __half* Hl = (__half*)(sm2 + RNN2_HL_OFF);
    __half* Wh = (__half*)(sm2 + RNN2_WH_OFF);
    __half* Wl = (__half*)(sm2 + RNN2_WL_OFF);

    const int tid  = threadIdx.x;
    const int bid  = blockIdx.x;
    const int d    = bid >> 6;
    const int n0   = (bid & 63) * 16;
    const int kq   = tid >> 5;        // 0..15, k-slice [kq*64, +64)
    const int lane = tid & 31;
    const int gid  = lane >> 2;
    const int tig  = lane & 3;

    // prologue: split W into hi fp16 + lo fp16 (x2048), layout [n][k]
    for (int i = tid; i < 16384; i += 512) {
        const int n = i >> 10, k = i & 1023;
        const float w = Whh[(size_t)(d * 1024 + n0 + n) * 1024 + k];
        const __half hi = __float2half_rn(w);
        Wh[n * RNP + k] = hi;
        Wl[n * RNP + k] = __float2half_rn((w - __half2float(hi)) * 2048.0f);
    }
    __syncthreads();

    // step-invariant epilogue terms
    const int eb   = tid >> 4;
    const int encl = n0 + (tid & 15);
    const int ecol = d * 1024 + encl;
    const float bb = bih[ecol] + bhh[ecol];
    float gB = 0.f;
    if (layer == 0) gB = gate[(size_t)eb * 2048 + ecol];

    unsigned bar_sense = 0;
    unsigned* bcount = &g_bar_count2[d];
    unsigned* bsense = &g_bar_sense2[d];

    for (int s = 1; s <= T_LEN; s++) {
        const int t = d ? (T_LEN - s) : (s - 1);

        float gT;
        if (layer == 0) gT = gate[(size_t)(32 + t) * 2048 + ecol];
        else            gT = gate[(size_t)(t * 32 + eb) * 2048 + ecol];

        // ---- each warp copies its 64-wide k-slice of both h planes ----
        const __half* srcH = HBh + ((s - 1) & 1) * 131072 + d * 65536;
        const __half* srcL = srcH + 32768;
        for (int j = lane; j < 256; j += 32) {
            const int b = j >> 3, u = j & 7;     // 8 uint4 per 64-half row slice
            const int go = b * 1024 + kq * 64 + u * 8;
            const int so = b * RNP + kq * 64 + u * 8;
            *(uint4*)&Hh[so] = *(const uint4*)&srcH[go];
            *(uint4*)&Hl[so] = *(const uint4*)&srcL[go];
        }
        __syncwarp();

        // ---- fp16 2-term mma over k-slice [kq*64, +64) ----
        float acc1[2][2][4], acc2[2][2][4];
#pragma unroll
        for (int i = 0; i < 2; i++)
#pragma unroll
            for (int j = 0; j < 2; j++)
#pragma unroll
                for (int r = 0; r < 4; r++) { acc1[i][j][r] = 0.f; acc2[i][j][r] = 0.f; }

#pragma unroll
        for (int kf = 0; kf < 4; kf++) {
            const int kk = kq * 64 + kf * 16;
            unsigned ahi[2][4], alo[2][4];
#pragma unroll
            for (int mt = 0; mt < 2; mt++) {
                const int r0 = (mt * 16 + gid) * RNP + kk + tig * 2;
                const int r1 = (mt * 16 + gid + 8) * RNP + kk + tig * 2;
                ahi[mt][0] = *(const unsigned*)&Hh[r0];
                ahi[mt][1] = *(const unsigned*)&Hh[r1];
                ahi[mt][2] = *(const unsigned*)&Hh[r0 + 8];
                ahi[mt][3] = *(const unsigned*)&Hh[r1 + 8];
                alo[mt][0] = *(const unsigned*)&Hl[r0];
                alo[mt][1] = *(const unsigned*)&Hl[r1];
                alo[mt][2] = *(const unsigned*)&Hl[r0 + 8];
                alo[mt][3] = *(const unsigned*)&Hl[r1 + 8];
            }
            unsigned bhi[2][2], blo[2][2];
#pragma unroll
            for (int nt = 0; nt < 2; nt++) {
                const int c0 = (nt * 8 + gid) * RNP + kk + tig * 2;
                bhi[nt][0] = *(const unsigned*)&Wh[c0];
                bhi[nt][1] = *(const unsigned*)&Wh[c0 + 8];
                blo[nt][0] = *(const unsigned*)&Wl[c0];
                blo[nt][1] = *(const unsigned*)&Wl[c0 + 8];
            }
#pragma unroll
            for (int mt = 0; mt < 2; mt++)
#pragma unroll
                for (int nt = 0; nt < 2; nt++) {
                    mma_f16(acc1[mt][nt], ahi[mt], bhi[nt]);   // hi*hi
                    mma_f16(acc2[mt][nt], alo[mt], bhi[nt]);   // lo*hi (x2048)
                    mma_f16(acc2[mt][nt], ahi[mt], blo[nt]);   // hi*lo (x2048)
                }
        }

        // ---- cross-warp k-reduction via Red (fp32, aliases Hh) ----
        __syncthreads();
        float* Red = (float*)Hh;   // Red[kq*512 + b*16 + n], 8192 floats = 32KB
#pragma unroll
        for (int mt = 0; mt < 2; mt++)
#pragma unroll
            for (int nt = 0; nt < 2; nt++)
#pragma unroll
                for (int r = 0; r < 4; r++) {
                    const int b = mt * 16 + gid + ((r >> 1) << 3);
                    const int n = nt * 8 + tig * 2 + (r & 1);
                    Red[kq * 512 + b * 16 + n] =
                        acc1[mt][nt][r] + acc2[mt][nt][r] * (1.0f / 2048.0f);
                }
        __syncthreads();

        // ---- epilogue: one output per thread ----
        {
            float v = 0.f;
#pragma unroll
            for (int kq2 = 0; kq2 < 16; kq2++) v += Red[kq2 * 512 + tid];
            const float hnew = fmaxf(v + gB + gT + bb, 0.f);
            const __half hhi = __float2half_rn(hnew);
            const __half hlo = __float2half_rn((hnew - __half2float(hhi)) * 2048.0f);
            __half* dstH = HBh + (s & 1) * 131072 + d * 65536;
            dstH[eb * 1024 + encl] = hhi;
            dstH[32768 + eb * 1024 + encl] = hlo;
            const int row = layer ? (eb * 128 + t) : (t * 32 + eb);
            Y[(size_t)row * 2048 + ecol] = hhi;
        }

        // ---- per-direction grid barrier (64 blocks, flat atomic sense reversal) ----
        __syncthreads();
        if (tid == 0) {
            const unsigned target = bar_sense ^ 1;
            unsigned old = atom_add_acqrel(bcount, 1);
            if (old == 63) {
                st_relaxed_u32(bcount, 0);
                st_release_u32(bsense, target);
            } else {
                while (ld_acquire_u32(bsense) != target) { }
            }
        }
        bar_sense ^= 1;
        __syncthreads();
    }
}

// ---------------- launch helpers ----------------
static inline void gemm_small(const float* A, const float* B, const float* bias,
                              float* C, int M, int N, int K)
{
    dim3 grid(N / 128, (M + 127) / 128);
    gemm_tf32_kernel<<<grid, 256>>>(A, B, bias, C, M, N, K);
}

typedef CUresult (CUDAAPI *PFN_encodeTiled)(
    CUtensorMap*, CUtensorMapDataType, cuuint32_t, void*,
    const cuuint64_t*, const cuuint64_t*, const cuuint32_t*, const cuuint32_t*,
    CUtensorMapInterleave, CUtensorMapSwizzle, CUtensorMapL2promotion,
    CUtensorMapFloatOOBfill);

static inline CUtensorMap make_map2d_f16(PFN_encodeTiled enc, const void* ptr,
                                         int rows, int K, int boxRows)
{
    CUtensorMap m{};
    cuuint64_t dims[2]    = {(cuuint64_t)K, (cuuint64_t)rows};
    cuuint64_t strides[1] = {(cuuint64_t)K * 2};
    cuuint32_t box[2]     = {64u, (cuuint32_t)boxRows};
    cuuint32_t es[2]      = {1u, 1u};
    enc(&m, CU_TENSOR_MAP_DATA_TYPE_UINT16, 2, (void*)ptr,
        dims, strides, box, es,
        CU_TENSOR_MAP_INTERLEAVE_NONE, CU_TENSOR_MAP_SWIZZLE_128B,
        CU_TENSOR_MAP_L2_PROMOTION_L2_128B, CU_TENSOR_MAP_FLOAT_OOB_FILL_NONE);
    return m;
}

extern "C" void kernel_launch(void* const* d_in, const int* in_sizes, int n_in,
                              void* d_out, int out_size)
{
    (void)in_sizes; (void)n_in; (void)out_size;
    const float* x     = (const float*)d_in[0];
    const float* W_exp = (const float*)d_in[1];
    const float* b_exp = (const float*)d_in[2];
    const float* g1    = (const float*)d_in[3];
    const float* be1   = (const float*)d_in[4];
    const float* pos   = (const float*)d_in[5];
    const float* Wih0  = (const float*)d_in[6];
    const float* Whh0  = (const float*)d_in[7];
    const float* bih0  = (const float*)d_in[8];
    const float* bhh0  = (const float*)d_in[9];
    const float* Wih1  = (const float*)d_in[10];
    const float* Whh1  = (const float*)d_in[11];
    const float* bih1  = (const float*)d_in[12];
    const float* bhh1  = (const float*)d_in[13];
    const float* Wp1   = (const float*)d_in[14];
    const float* bp1   = (const float*)d_in[15];
    const float* g2    = (const float*)d_in[16];
    const float* be2   = (const float*)d_in[17];
    const float* Wp2   = (const float*)d_in[18];
    const float* bp2   = (const float*)d_in[19];
    float* out = (float*)d_out;

    float* S = nullptr;
    cudaGetSymbolAddress((void**)&S, g_scratch);

    float*  PRE   = S + OFF_PRE;
    float*  EXP   = S + OFF_EXP;
    __half* A0INH = (__half*)(S + OFF_A0INH);
    float*  C0    = S + OFF_C0;
    __half* HBh   = (__half*)(S + OFF_HB);
    __half* X1H   = (__half*)(S + OFF_X1H);
    float*  G1    = S + OFF_G1;
    __half* OUT2H = (__half*)(S + OFF_OUT2H);
    float*  PROJ  = S + OFF_PROJ;
    __half* HEH   = (__half*)(S + OFF_HEH);
    __half* WIH1H = (__half*)(S + OFF_WIH1H);
    __half* WP1H  = (__half*)(S + OFF_WP1H);
    __half* WP2H  = (__half*)(S + OFF_WP2H);
    __half* WIH0H = (__half*)(S + OFF_WIH0H);

    PFN_encodeTiled enc = nullptr;
    cudaGetDriverEntryPoint("cuTensorMapEncodeTiled", (void**)&enc, cudaEnableDefault);

    CUtensorMap tmA_C0  = make_map2d_f16(enc, A0INH, 160,   1024, 128);
    CUtensorMap tmB_C0  = make_map2d_f16(enc, WIH0H, 2048,  1024, 256);
    CUtensorMap tmA_G1  = make_map2d_f16(enc, X1H,   4096,  2048, 128);
    CUtensorMap tmB_G1  = make_map2d_f16(enc, WIH1H, 2048,  2048, 256);
    CUtensorMap tmA_PRJ = make_map2d_f16(enc, OUT2H, 4096,  2048, 128);
    CUtensorMap tmB_PRJ = make_map2d_f16(enc, WP1H,  512,   2048, 256);
    CUtensorMap tmA_LOG = make_map2d_f16(enc, HEH,   4096,  512,  128);
    CUtensorMap tmB_LOG = make_map2d_f16(enc, WP2H,  32000, 512,  256);

    cudaFuncSetAttribute(rnn_layer_kernel,
                         cudaFuncAttributeMaxDynamicSharedMemorySize, RNN2_SMEM_BYTES);
    cudaFuncSetAttribute(gemm_tma_f16_kernel,
                         cudaFuncAttributeMaxDynamicSharedMemorySize, TG_SMEM_BYTES);

    // 0) pre-convert weights to fp16
    tohalf_kernel<<<512, 256>>>(Wih1, (__half2*)WIH1H, 2 * 1024 * 2048 / 4);
    tohalf_kernel<<<512, 256>>>(Wp1,  (__half2*)WP1H,  512 * 2048 / 4);
    tohalf_kernel<<<512, 256>>>(Wp2,  (__half2*)WP2H,  32000 * 512 / 4);
    tohalf_kernel<<<512, 256>>>(Wih0, (__half2*)WIH0H, 2 * 1024 * 1024 / 4);

    // 1) expand (proven tf32 tile) + LN/ReLU
    gemm_small(x, W_exp, b_exp, PRE, 32, 1024, 512);
    ln_relu_kernel<<<32, 256>>>(PRE, g1, be1, EXP, 1024);

    // 2) layer-0 gate factors (fp16 TMA GEMM, M padded to 256 via TMA OOB zero-fill)
    concat_f16_kernel<<<640, 256>>>(EXP, pos, A0INH);
    {
        dim3 grid(2048 / 256, 2);   // M = 256 (rows >= 160 dead)
        gemm_tma_f16_kernel<<<grid, 512, TG_SMEM_BYTES>>>(tmA_C0, tmB_C0, nullptr, C0, 2048, 1024);
    }

    // 3) layer-0 recurrence (persistent, fp16 2-term), writes X1 as fp16
    pack_h0_kernel<<<128, 256>>>(EXP, HBh);
    rnn_layer_kernel<<<128, 512, RNN2_SMEM_BYTES>>>(Whh0, C0, bih0, bhh0, HBh, X1H, 0);

    // 4) layer-1 gates (fp16 TMA GEMM): G1[4096,2048] fp32 out
    {
        dim3 grid(2048 / 256, 4096 / 128);
        gemm_tma_f16_kernel<<<grid, 512, TG_SMEM_BYTES>>>(tmA_G1, tmB_G1, nullptr, G1, 2048, 2048);
    }

    // 5) layer-1 recurrence (persistent, fp16 2-term), writes OUT2 as fp16
    pack_h0_kernel<<<128, 256>>>(EXP, HBh);
    rnn_layer_kernel<<<128, 512, RNN2_SMEM_BYTES>>>(Whh1, G1, bih1, bhh1, HBh, OUT2H, 1);

    // 6) projection head (fp16 TMA GEMM) + LN+ReLU -> fp16
    {
        dim3 grid(512 / 256, 4096 / 128);
        gemm_tma_f16_kernel<<<grid, 512, TG_SMEM_BYTES>>>(tmA_PRJ, tmB_PRJ, bp1, PROJ, 512, 2048);
    }
    ln_relu_f16_kernel<<<4096, 256>>>(PROJ, g2, be2, HEH, 512);

    // 7) logits (fp16 TMA GEMM)
    {
        dim3 grid(32000 / 256, 4096 / 128);
        gemm_tma_f16_kernel<<<grid, 512, TG_SMEM_BYTES>>>(tmA_LOG, tmB_LOG, bp2, out, 32000, 512);
    }
}